// round 2
// baseline (speedup 1.0000x reference)
#include <cuda_runtime.h>
#include <cstdint>

#define B_   8
#define S_   4096
#define D_   1024
#define R_   256
#define BS_  (B_*S_)        // 32768
#define NCH  64
#define CHUNK 64            // NCH*CHUNK == S_

// ---- device scratch (no allocations allowed) ----
__device__ float g_xm[B_*D_];          // column sums of x over s (divided by S later)
__device__ float g_rnorm[BS_];         // 1/max(||x_row||, eps)
__device__ float g_fnorm[R_*D_];       // L2-normalized frequencies, tf32-rounded
__device__ float g_gate[B_*R_];        // hard-thresholded gate
__device__ float g_ret[B_*R_];         // retention
__device__ float g_sig[(size_t)BS_*R_]; // signal -> in-place scan -> accumulated
__device__ float g_carry[B_*NCH*R_];   // per-chunk scan carries

__device__ __forceinline__ uint32_t f2tf32(float v) {
    uint32_t u;
    asm("cvt.rna.tf32.f32 %0, %1;" : "=r"(u) : "f"(v));
    return u;
}

__device__ __forceinline__ void mma_tf32(float c[4], uint32_t a0, uint32_t a1,
                                         uint32_t a2, uint32_t a3,
                                         uint32_t b0, uint32_t b1) {
    asm volatile(
        "mma.sync.aligned.m16n8k8.row.col.f32.tf32.tf32.f32 "
        "{%0,%1,%2,%3}, {%4,%5,%6,%7}, {%8,%9}, {%0,%1,%2,%3};"
        : "+f"(c[0]), "+f"(c[1]), "+f"(c[2]), "+f"(c[3])
        : "r"(a0), "r"(a1), "r"(a2), "r"(a3), "r"(b0), "r"(b1));
}

// ---- K0: zero xm accumulator ----
__global__ void k0_zero() {
    int i = blockIdx.x * 1024 + threadIdx.x;
    if (i < B_*D_) g_xm[i] = 0.f;
}

// ---- K1: per-row inverse norms + column sums (for mean) ----
__global__ __launch_bounds__(256) void k1_stats(const float* __restrict__ x) {
    __shared__ float sxm[8][D_];   // 32KB
    int blk  = blockIdx.x;         // 256 blocks, 128 rows each (never crosses b)
    int warp = threadIdx.x >> 5, lane = threadIdx.x & 31;
    float cs[32];
#pragma unroll
    for (int k = 0; k < 32; k++) cs[k] = 0.f;
    int row0 = blk * 128 + warp * 16;
    for (int rr = 0; rr < 16; rr++) {
        int row = row0 + rr;
        const float* xr = x + (size_t)row * D_;
        float ss = 0.f;
#pragma unroll
        for (int k = 0; k < 32; k++) {
            float v = xr[lane + 32*k];
            cs[k] += v;
            ss = fmaf(v, v, ss);
        }
#pragma unroll
        for (int o = 16; o > 0; o >>= 1) ss += __shfl_xor_sync(0xffffffffu, ss, o);
        if (lane == 0) g_rnorm[row] = 1.f / fmaxf(sqrtf(ss), 1e-12f);
    }
#pragma unroll
    for (int k = 0; k < 32; k++) sxm[warp][lane + 32*k] = cs[k];
    __syncthreads();
    int b = (blk * 128) / S_;
    for (int d = threadIdx.x; d < D_; d += 256) {
        float s = 0.f;
#pragma unroll
        for (int w = 0; w < 8; w++) s += sxm[w][d];
        atomicAdd(&g_xm[b*D_ + d], s);
    }
}

// ---- K2: f_norm (tf32-rounded) + gate + retention ----
__global__ __launch_bounds__(256) void k2_prep(const float* __restrict__ freq,
                                               const float* __restrict__ rbias,
                                               const float* __restrict__ rw,
                                               const float* __restrict__ gw,
                                               const float* __restrict__ gbias) {
    int r = blockIdx.x;
    int t = threadIdx.x, warp = t >> 5, lane = t & 31;
    __shared__ float red[256];

    // --- normalize frequencies row r ---
    const float* fr = freq + (size_t)r * D_;
    float fv[4]; float ss = 0.f;
#pragma unroll
    for (int i = 0; i < 4; i++) { fv[i] = fr[t + 256*i]; ss = fmaf(fv[i], fv[i], ss); }
    red[t] = ss; __syncthreads();
    if (t < 128) red[t] += red[t+128]; __syncthreads();
    if (t < 64)  red[t] += red[t+64];  __syncthreads();
    if (t < 32) {
        float v = red[t] + red[t+32];
#pragma unroll
        for (int o = 16; o > 0; o >>= 1) v += __shfl_xor_sync(0xffffffffu, v, o);
        if (t == 0) red[0] = v;
    }
    __syncthreads();
    float inv = 1.f / fmaxf(sqrtf(red[0]), 1e-12f);
#pragma unroll
    for (int i = 0; i < 4; i++)
        g_fnorm[(size_t)r*D_ + t + 256*i] = __uint_as_float(f2tf32(fv[i] * inv));

    // --- gate + retention: warp w handles batch b=w ---
    int b = warp;  // 8 warps, 8 batches
    const float* gwr = gw + (size_t)r * D_;
    const float* rwr = rw + (size_t)r * D_;
    float ag = 0.f, ar = 0.f;
    const float invS = 1.f / (float)S_;
    for (int k = lane; k < D_; k += 32) {
        float xm = g_xm[b*D_ + k] * invS;
        ag = fmaf(xm, gwr[k], ag);
        ar = fmaf(xm, rwr[k], ar);
    }
#pragma unroll
    for (int o = 16; o > 0; o >>= 1) {
        ag += __shfl_xor_sync(0xffffffffu, ag, o);
        ar += __shfl_xor_sync(0xffffffffu, ar, o);
    }
    if (lane == 0) {
        float gl = ag + gbias[r];
        float gs = 1.f / (1.f + expf(-gl));
        g_gate[b*R_ + r] = (gs >= 0.001f) ? gs : 0.f;   // straight-through hard gate
        float rl = ar + rbias[r];
        g_ret[b*R_ + r] = 1.f / (1.f + expf(-rl));
    }
}

// ---- K3: resonance GEMM (tf32) + scale by rnorm*gate -> g_sig ----
// grid (2, 256): x = n-tile (fast), y = m-tile so both n-tiles of an m hit L2 on A.
#define LDT 36
__global__ __launch_bounds__(256) void k3_resonance(const float* __restrict__ x) {
    __shared__ float As[128*LDT];
    __shared__ float Bs[128*LDT];
    int nbase = blockIdx.x * 128;
    int mbase = blockIdx.y * 128;
    int t = threadIdx.x;
    int warp = t >> 5, lane = t & 31;
    int wm = warp >> 2, wn = warp & 3;       // 2 x 4 warp grid; warp tile 64x32
    int grp = lane >> 2, tid4 = lane & 3;

    float c[4][4][4];
#pragma unroll
    for (int mt = 0; mt < 4; mt++)
#pragma unroll
        for (int nt = 0; nt < 4; nt++)
#pragma unroll
            for (int i = 0; i < 4; i++) c[mt][nt][i] = 0.f;

    int lrow = t >> 3;          // 0..31
    int lk   = (t & 7) * 4;     // 0..28

    for (int k0 = 0; k0 < D_; k0 += 32) {
#pragma unroll
        for (int i = 0; i < 4; i++) {
            int row = lrow + i*32;
            float4 va = *(const float4*)(x + (size_t)(mbase+row)*D_ + k0 + lk);
            float* da = &As[row*LDT + lk];
            da[0] = __uint_as_float(f2tf32(va.x));
            da[1] = __uint_as_float(f2tf32(va.y));
            da[2] = __uint_as_float(f2tf32(va.z));
            da[3] = __uint_as_float(f2tf32(va.w));
            float4 vb = *(const float4*)(g_fnorm + (size_t)(nbase+row)*D_ + k0 + lk);
            float* db = &Bs[row*LDT + lk];
            db[0] = vb.x; db[1] = vb.y; db[2] = vb.z; db[3] = vb.w;  // already tf32
        }
        __syncthreads();
#pragma unroll
        for (int kk = 0; kk < 4; kk++) {
            int ko = kk * 8;
            uint32_t a[4][4], bf[4][2];
#pragma unroll
            for (int mt = 0; mt < 4; mt++) {
                int m0 = wm*64 + mt*16;
                a[mt][0] = __float_as_uint(As[(m0+grp)*LDT   + ko + tid4]);
                a[mt][1] = __float_as_uint(As[(m0+8+grp)*LDT + ko + tid4]);
                a[mt][2] = __float_as_uint(As[(m0+grp)*LDT   + ko + tid4 + 4]);
                a[mt][3] = __float_as_uint(As[(m0+8+grp)*LDT + ko + tid4 + 4]);
            }
#pragma unroll
            for (int nt = 0; nt < 4; nt++) {
                int n0 = wn*32 + nt*8;
                bf[nt][0] = __float_as_uint(Bs[(n0+grp)*LDT + ko + tid4]);
                bf[nt][1] = __float_as_uint(Bs[(n0+grp)*LDT + ko + tid4 + 4]);
            }
#pragma unroll
            for (int mt = 0; mt < 4; mt++)
#pragma unroll
                for (int nt = 0; nt < 4; nt++)
                    mma_tf32(c[mt][nt], a[mt][0], a[mt][1], a[mt][2], a[mt][3],
                             bf[nt][0], bf[nt][1]);
        }
        __syncthreads();
    }

    int b = mbase / S_;
#pragma unroll
    for (int mt = 0; mt < 4; mt++) {
        int m0 = mbase + wm*64 + mt*16 + grp;
        float rn0 = g_rnorm[m0], rn1 = g_rnorm[m0+8];
#pragma unroll
        for (int nt = 0; nt < 4; nt++) {
            int n = nbase + wn*32 + nt*8 + tid4*2;
            float gg0 = g_gate[b*R_ + n], gg1 = g_gate[b*R_ + n + 1];
            float2 v0 = make_float2(c[mt][nt][0]*rn0*gg0, c[mt][nt][1]*rn0*gg1);
            float2 v1 = make_float2(c[mt][nt][2]*rn1*gg0, c[mt][nt][3]*rn1*gg1);
            *(float2*)&g_sig[(size_t)m0*R_ + n]     = v0;
            *(float2*)&g_sig[(size_t)(m0+8)*R_ + n] = v1;
        }
    }
}

// ---- K4a: chunk-local scan (in place), emit carries ----
__global__ __launch_bounds__(256) void k_scan1() {
    int blk = blockIdx.x;           // b*NCH + chunk
    int b = blk / NCH, ch = blk % NCH;
    int r = threadIdx.x;
    float ret = g_ret[b*R_ + r];
    size_t base = ((size_t)(b*S_ + ch*CHUNK)) * R_ + r;
    float st = 0.f;
    for (int g = 0; g < CHUNK/8; g++) {
        float v[8];
#pragma unroll
        for (int j = 0; j < 8; j++) v[j] = g_sig[base + (size_t)(g*8+j)*R_];
#pragma unroll
        for (int j = 0; j < 8; j++) {
            st = fmaf(st, ret, v[j]);
            g_sig[base + (size_t)(g*8+j)*R_] = st;
        }
    }
    g_carry[(b*NCH + ch)*R_ + r] = st;
}

// ---- K4b: apply chunk prefixes; emit final_state ----
__global__ __launch_bounds__(256) void k_scan2(const float* __restrict__ prev,
                                               float* __restrict__ fs_out,
                                               int write_fs) {
    int blk = blockIdx.x;
    int b = blk / NCH, ch = blk % NCH;
    int r = threadIdx.x;
    float ret = g_ret[b*R_ + r];
    float q = ret;
#pragma unroll
    for (int i = 0; i < 6; i++) q = q * q;   // ret^64 == ret^CHUNK
    float e = prev[b*R_ + r];
    for (int j = 0; j < ch; j++)
        e = fmaf(e, q, g_carry[(b*NCH + j)*R_ + r]);

    size_t base = ((size_t)(b*S_ + ch*CHUNK)) * R_ + r;
    float p = ret;
    float last = 0.f;
    for (int g = 0; g < CHUNK/8; g++) {
        float v[8];
#pragma unroll
        for (int j = 0; j < 8; j++) v[j] = g_sig[base + (size_t)(g*8+j)*R_];
#pragma unroll
        for (int j = 0; j < 8; j++) {
            float o = fmaf(e, p, v[j]);
            g_sig[base + (size_t)(g*8+j)*R_] = o;
            p *= ret;
            last = o;
        }
    }
    if (write_fs && ch == NCH-1)
        fs_out[b*R_ + r] = last;
}

// ---- K5: output GEMM (tf32): acc (M x 256) * out_w^T (256 x 1024) ----
// grid (8, 256): x = n-tile fast so 8 n-tiles of one m-tile reuse A via L2.
__global__ __launch_bounds__(256) void k5_output(const float* __restrict__ outw,
                                                 float* __restrict__ out) {
    __shared__ float As[128*LDT];
    __shared__ float Bs[128*LDT];
    int nbase = blockIdx.x * 128;
    int mbase = blockIdx.y * 128;
    int t = threadIdx.x;
    int warp = t >> 5, lane = t & 31;
    int wm = warp >> 2, wn = warp & 3;
    int grp = lane >> 2, tid4 = lane & 3;

    float c[4][4][4];
#pragma unroll
    for (int mt = 0; mt < 4; mt++)
#pragma unroll
        for (int nt = 0; nt < 4; nt++)
#pragma unroll
            for (int i = 0; i < 4; i++) c[mt][nt][i] = 0.f;

    int lrow = t >> 3;
    int lk   = (t & 7) * 4;

    for (int k0 = 0; k0 < R_; k0 += 32) {
#pragma unroll
        for (int i = 0; i < 4; i++) {
            int row = lrow + i*32;
            float4 va = *(const float4*)(g_sig + (size_t)(mbase+row)*R_ + k0 + lk);
            float* da = &As[row*LDT + lk];
            da[0] = __uint_as_float(f2tf32(va.x));
            da[1] = __uint_as_float(f2tf32(va.y));
            da[2] = __uint_as_float(f2tf32(va.z));
            da[3] = __uint_as_float(f2tf32(va.w));
            float4 vb = *(const float4*)(outw + (size_t)(nbase+row)*R_ + k0 + lk);
            float* db = &Bs[row*LDT + lk];
            db[0] = __uint_as_float(f2tf32(vb.x));
            db[1] = __uint_as_float(f2tf32(vb.y));
            db[2] = __uint_as_float(f2tf32(vb.z));
            db[3] = __uint_as_float(f2tf32(vb.w));
        }
        __syncthreads();
#pragma unroll
        for (int kk = 0; kk < 4; kk++) {
            int ko = kk * 8;
            uint32_t a[4][4], bf[4][2];
#pragma unroll
            for (int mt = 0; mt < 4; mt++) {
                int m0 = wm*64 + mt*16;
                a[mt][0] = __float_as_uint(As[(m0+grp)*LDT   + ko + tid4]);
                a[mt][1] = __float_as_uint(As[(m0+8+grp)*LDT + ko + tid4]);
                a[mt][2] = __float_as_uint(As[(m0+grp)*LDT   + ko + tid4 + 4]);
                a[mt][3] = __float_as_uint(As[(m0+8+grp)*LDT + ko + tid4 + 4]);
            }
#pragma unroll
            for (int nt = 0; nt < 4; nt++) {
                int n0 = wn*32 + nt*8;
                bf[nt][0] = __float_as_uint(Bs[(n0+grp)*LDT + ko + tid4]);
                bf[nt][1] = __float_as_uint(Bs[(n0+grp)*LDT + ko + tid4 + 4]);
            }
#pragma unroll
            for (int mt = 0; mt < 4; mt++)
#pragma unroll
                for (int nt = 0; nt < 4; nt++)
                    mma_tf32(c[mt][nt], a[mt][0], a[mt][1], a[mt][2], a[mt][3],
                             bf[nt][0], bf[nt][1]);
        }
        __syncthreads();
    }

#pragma unroll
    for (int mt = 0; mt < 4; mt++) {
        int m0 = mbase + wm*64 + mt*16 + grp;
#pragma unroll
        for (int nt = 0; nt < 4; nt++) {
            int n = nbase + wn*32 + nt*8 + tid4*2;
            float2 v0 = make_float2(c[mt][nt][0], c[mt][nt][1]);
            float2 v1 = make_float2(c[mt][nt][2], c[mt][nt][3]);
            *(float2*)&out[(size_t)m0*D_ + n]     = v0;
            *(float2*)&out[(size_t)(m0+8)*D_ + n] = v1;
        }
    }
}

extern "C" void kernel_launch(void* const* d_in, const int* in_sizes, int n_in,
                              void* d_out, int out_size) {
    const float* x     = (const float*)d_in[0];
    const float* prev  = (const float*)d_in[1];
    const float* freq  = (const float*)d_in[2];
    const float* rbias = (const float*)d_in[3];
    const float* rw    = (const float*)d_in[4];
    const float* gw    = (const float*)d_in[5];
    const float* gbias = (const float*)d_in[6];
    const float* outw  = (const float*)d_in[7];
    float* out = (float*)d_out;

    const int out_elems = B_*S_*D_;
    int write_fs = (out_size >= out_elems + B_*R_) ? 1 : 0;
    float* fs = out + out_elems;

    k0_zero<<<8, 1024>>>();
    k1_stats<<<256, 256>>>(x);
    k2_prep<<<256, 256>>>(freq, rbias, rw, gw, gbias);
    k3_resonance<<<dim3(2, 256), 256>>>(x);
    k_scan1<<<B_*NCH, 256>>>();
    k_scan2<<<B_*NCH, 256>>>(prev, fs, write_fs);
    k5_output<<<dim3(8, 256), 256>>>(outw, out);
}

// round 3
// speedup vs baseline: 1.1458x; 1.1458x over previous
#include <cuda_runtime.h>
#include <cstdint>

#define B_   8
#define S_   4096
#define D_   1024
#define R_   256
#define BS_  (B_*S_)        // 32768
#define NCH  64
#define CHUNK 64            // NCH*CHUNK == S_
#define LDT  36
#define STAGE_F (128*LDT)   // floats per stage per operand

// ---- device scratch (no allocations allowed) ----
__device__ float g_xm[B_*D_];
__device__ float g_rnorm[BS_];
__device__ float g_fnorm[R_*D_];        // L2-normalized freqs, tf32-rounded
__device__ float g_gate[B_*R_];
__device__ float g_ret[B_*R_];
__device__ float g_sig[(size_t)BS_*R_]; // signal -> scan -> accumulated(tf32)
__device__ float g_carry[B_*NCH*R_];
__device__ float g_outwt[D_*R_];        // tf32-rounded out_w

__device__ __forceinline__ uint32_t f2tf32(float v) {
    uint32_t u;
    asm("cvt.rna.tf32.f32 %0, %1;" : "=r"(u) : "f"(v));
    return u;
}

__device__ __forceinline__ void mma_tf32(float c[4], uint32_t a0, uint32_t a1,
                                         uint32_t a2, uint32_t a3,
                                         uint32_t b0, uint32_t b1) {
    asm volatile(
        "mma.sync.aligned.m16n8k8.row.col.f32.tf32.tf32.f32 "
        "{%0,%1,%2,%3}, {%4,%5,%6,%7}, {%8,%9}, {%0,%1,%2,%3};"
        : "+f"(c[0]), "+f"(c[1]), "+f"(c[2]), "+f"(c[3])
        : "r"(a0), "r"(a1), "r"(a2), "r"(a3), "r"(b0), "r"(b1));
}

__device__ __forceinline__ void cp16(uint32_t smem_dst, const void* gptr) {
    asm volatile("cp.async.cg.shared.global [%0], [%1], 16;\n"
                 :: "r"(smem_dst), "l"(gptr));
}

// ---- K0: zero xm accumulator ----
__global__ void k0_zero() {
    int i = blockIdx.x * 1024 + threadIdx.x;
    if (i < B_*D_) g_xm[i] = 0.f;
}

// ---- K1: per-row inverse norms + column sums (for mean) ----
__global__ __launch_bounds__(256) void k1_stats(const float* __restrict__ x) {
    __shared__ float sxm[8][D_];   // 32KB
    int blk  = blockIdx.x;         // 256 blocks, 128 rows each
    int warp = threadIdx.x >> 5, lane = threadIdx.x & 31;
    float cs[32];
#pragma unroll
    for (int k = 0; k < 32; k++) cs[k] = 0.f;
    int row0 = blk * 128 + warp * 16;
    for (int rr = 0; rr < 16; rr++) {
        int row = row0 + rr;
        const float* xr = x + (size_t)row * D_;
        float ss = 0.f;
#pragma unroll
        for (int k = 0; k < 32; k++) {
            float v = xr[lane + 32*k];
            cs[k] += v;
            ss = fmaf(v, v, ss);
        }
#pragma unroll
        for (int o = 16; o > 0; o >>= 1) ss += __shfl_xor_sync(0xffffffffu, ss, o);
        if (lane == 0) g_rnorm[row] = 1.f / fmaxf(sqrtf(ss), 1e-12f);
    }
#pragma unroll
    for (int k = 0; k < 32; k++) sxm[warp][lane + 32*k] = cs[k];
    __syncthreads();
    int b = (blk * 128) / S_;
    for (int d = threadIdx.x; d < D_; d += 256) {
        float s = 0.f;
#pragma unroll
        for (int w = 0; w < 8; w++) s += sxm[w][d];
        atomicAdd(&g_xm[b*D_ + d], s);
    }
}

// ---- K2: f_norm (tf32-rounded) + gate + retention ----
__global__ __launch_bounds__(256) void k2_prep(const float* __restrict__ freq,
                                               const float* __restrict__ rbias,
                                               const float* __restrict__ rw,
                                               const float* __restrict__ gw,
                                               const float* __restrict__ gbias) {
    int r = blockIdx.x;
    int t = threadIdx.x, warp = t >> 5, lane = t & 31;
    __shared__ float red[256];

    const float* fr = freq + (size_t)r * D_;
    float fv[4]; float ss = 0.f;
#pragma unroll
    for (int i = 0; i < 4; i++) { fv[i] = fr[t + 256*i]; ss = fmaf(fv[i], fv[i], ss); }
    red[t] = ss; __syncthreads();
    if (t < 128) red[t] += red[t+128]; __syncthreads();
    if (t < 64)  red[t] += red[t+64];  __syncthreads();
    if (t < 32) {
        float v = red[t] + red[t+32];
#pragma unroll
        for (int o = 16; o > 0; o >>= 1) v += __shfl_xor_sync(0xffffffffu, v, o);
        if (t == 0) red[0] = v;
    }
    __syncthreads();
    float inv = 1.f / fmaxf(sqrtf(red[0]), 1e-12f);
#pragma unroll
    for (int i = 0; i < 4; i++)
        g_fnorm[(size_t)r*D_ + t + 256*i] = __uint_as_float(f2tf32(fv[i] * inv));

    int b = warp;  // 8 warps, 8 batches
    const float* gwr = gw + (size_t)r * D_;
    const float* rwr = rw + (size_t)r * D_;
    float ag = 0.f, ar = 0.f;
    const float invS = 1.f / (float)S_;
    for (int k = lane; k < D_; k += 32) {
        float xm = g_xm[b*D_ + k] * invS;
        ag = fmaf(xm, gwr[k], ag);
        ar = fmaf(xm, rwr[k], ar);
    }
#pragma unroll
    for (int o = 16; o > 0; o >>= 1) {
        ag += __shfl_xor_sync(0xffffffffu, ag, o);
        ar += __shfl_xor_sync(0xffffffffu, ar, o);
    }
    if (lane == 0) {
        float gl = ag + gbias[r];
        float gs = 1.f / (1.f + expf(-gl));
        g_gate[b*R_ + r] = (gs >= 0.001f) ? gs : 0.f;
        float rl = ar + rbias[r];
        g_ret[b*R_ + r] = 1.f / (1.f + expf(-rl));
    }
}

// ---- K2b: pre-round out_w to tf32 ----
__global__ void k2b_roundw(const float* __restrict__ outw) {
    int i = blockIdx.x * 256 + threadIdx.x;
    g_outwt[i] = __uint_as_float(f2tf32(outw[i]));
}

// ============ pipelined tf32 GEMM core (shared by k3/k5) ============
// smem: As[2][128*LDT], Bs[2][128*LDT]  (dynamic, 72KB)
// thread copy map: lrow=t>>3 (0..31), lk=(t&7)*4; rows lrow+i*32
struct Frag { float c[4][4][4]; };

template<bool CVT_A>
__device__ __forceinline__ void gemm_compute_stage(const float* __restrict__ Asb,
                                                   const float* __restrict__ Bsb,
                                                   int wm, int wn, int grp, int tid4,
                                                   float c[4][4][4]) {
#pragma unroll
    for (int kk = 0; kk < 4; kk++) {
        int ko = kk * 8;
        uint32_t a[4][4], bf[4][2];
#pragma unroll
        for (int mt = 0; mt < 4; mt++) {
            int m0 = wm*64 + mt*16;
            if (CVT_A) {
                a[mt][0] = f2tf32(Asb[(m0+grp)*LDT   + ko + tid4]);
                a[mt][1] = f2tf32(Asb[(m0+8+grp)*LDT + ko + tid4]);
                a[mt][2] = f2tf32(Asb[(m0+grp)*LDT   + ko + tid4 + 4]);
                a[mt][3] = f2tf32(Asb[(m0+8+grp)*LDT + ko + tid4 + 4]);
            } else {
                a[mt][0] = __float_as_uint(Asb[(m0+grp)*LDT   + ko + tid4]);
                a[mt][1] = __float_as_uint(Asb[(m0+8+grp)*LDT + ko + tid4]);
                a[mt][2] = __float_as_uint(Asb[(m0+grp)*LDT   + ko + tid4 + 4]);
                a[mt][3] = __float_as_uint(Asb[(m0+8+grp)*LDT + ko + tid4 + 4]);
            }
        }
#pragma unroll
        for (int nt = 0; nt < 4; nt++) {
            int n0 = wn*32 + nt*8;
            bf[nt][0] = __float_as_uint(Bsb[(n0+grp)*LDT + ko + tid4]);
            bf[nt][1] = __float_as_uint(Bsb[(n0+grp)*LDT + ko + tid4 + 4]);
        }
#pragma unroll
        for (int mt = 0; mt < 4; mt++)
#pragma unroll
            for (int nt = 0; nt < 4; nt++)
                mma_tf32(c[mt][nt], a[mt][0], a[mt][1], a[mt][2], a[mt][3],
                         bf[nt][0], bf[nt][1]);
    }
}

// ---- K3: resonance GEMM + scale by rnorm*gate -> g_sig ----
__global__ __launch_bounds__(256) void k3_resonance(const float* __restrict__ x) {
    extern __shared__ float smem[];
    float* As = smem;
    float* Bs = smem + 2*STAGE_F;
    uint32_t as_b = (uint32_t)__cvta_generic_to_shared(As);
    uint32_t bs_b = (uint32_t)__cvta_generic_to_shared(Bs);

    int nbase = blockIdx.x * 128;
    int mbase = blockIdx.y * 128;
    int t = threadIdx.x;
    int warp = t >> 5, lane = t & 31;
    int wm = warp >> 2, wn = warp & 3;
    int grp = lane >> 2, tid4 = lane & 3;
    int lrow = t >> 3, lk = (t & 7) * 4;

    float c[4][4][4];
#pragma unroll
    for (int mt = 0; mt < 4; mt++)
#pragma unroll
        for (int nt = 0; nt < 4; nt++)
#pragma unroll
            for (int i = 0; i < 4; i++) c[mt][nt][i] = 0.f;

    const float* Ag = x + (size_t)mbase * D_;
    const float* Bg = g_fnorm + (size_t)nbase * D_;

    auto prefetch = [&](int st, int k0) {
        uint32_t ao = as_b + (uint32_t)(st*STAGE_F)*4u;
        uint32_t bo = bs_b + (uint32_t)(st*STAGE_F)*4u;
#pragma unroll
        for (int i = 0; i < 4; i++) {
            int row = lrow + i*32;
            cp16(ao + (uint32_t)(row*LDT + lk)*4u, Ag + (size_t)row*D_ + k0 + lk);
            cp16(bo + (uint32_t)(row*LDT + lk)*4u, Bg + (size_t)row*D_ + k0 + lk);
        }
        asm volatile("cp.async.commit_group;\n");
    };

    prefetch(0, 0);
    const int NK = D_ / 32;   // 32
    for (int kt = 0; kt < NK; kt++) {
        if (kt + 1 < NK) {
            prefetch((kt+1)&1, (kt+1)*32);
            asm volatile("cp.async.wait_group 1;\n");
        } else {
            asm volatile("cp.async.wait_group 0;\n");
        }
        __syncthreads();
        gemm_compute_stage<true>(As + (kt&1)*STAGE_F, Bs + (kt&1)*STAGE_F,
                                 wm, wn, grp, tid4, c);
        __syncthreads();
    }

    int b = mbase / S_;
#pragma unroll
    for (int mt = 0; mt < 4; mt++) {
        int m0 = mbase + wm*64 + mt*16 + grp;
        float rn0 = g_rnorm[m0], rn1 = g_rnorm[m0+8];
#pragma unroll
        for (int nt = 0; nt < 4; nt++) {
            int n = nbase + wn*32 + nt*8 + tid4*2;
            float gg0 = g_gate[b*R_ + n], gg1 = g_gate[b*R_ + n + 1];
            float2 v0 = make_float2(c[mt][nt][0]*rn0*gg0, c[mt][nt][1]*rn0*gg1);
            float2 v1 = make_float2(c[mt][nt][2]*rn1*gg0, c[mt][nt][3]*rn1*gg1);
            *(float2*)&g_sig[(size_t)m0*R_ + n]     = v0;
            *(float2*)&g_sig[(size_t)(m0+8)*R_ + n] = v1;
        }
    }
}

// ---- K4a: chunk-local scan (in place), emit carries ----
__global__ __launch_bounds__(256) void k_scan1() {
    int blk = blockIdx.x;
    int b = blk / NCH, ch = blk % NCH;
    int r = threadIdx.x;
    float ret = g_ret[b*R_ + r];
    size_t base = ((size_t)(b*S_ + ch*CHUNK)) * R_ + r;
    float st = 0.f;
    for (int g = 0; g < CHUNK/8; g++) {
        float v[8];
#pragma unroll
        for (int j = 0; j < 8; j++) v[j] = g_sig[base + (size_t)(g*8+j)*R_];
#pragma unroll
        for (int j = 0; j < 8; j++) {
            st = fmaf(st, ret, v[j]);
            g_sig[base + (size_t)(g*8+j)*R_] = st;
        }
    }
    g_carry[(b*NCH + ch)*R_ + r] = st;
}

// ---- K4b: apply chunk prefixes; store tf32-rounded acc; emit final_state ----
__global__ __launch_bounds__(256) void k_scan2(const float* __restrict__ prev,
                                               float* __restrict__ fs_out,
                                               int write_fs) {
    int blk = blockIdx.x;
    int b = blk / NCH, ch = blk % NCH;
    int r = threadIdx.x;
    float ret = g_ret[b*R_ + r];
    float q = ret;
#pragma unroll
    for (int i = 0; i < 6; i++) q = q * q;   // ret^64
    float e = prev[b*R_ + r];
    for (int j = 0; j < ch; j++)
        e = fmaf(e, q, g_carry[(b*NCH + j)*R_ + r]);

    size_t base = ((size_t)(b*S_ + ch*CHUNK)) * R_ + r;
    float p = ret;
    float last = 0.f;
    for (int g = 0; g < CHUNK/8; g++) {
        float v[8];
#pragma unroll
        for (int j = 0; j < 8; j++) v[j] = g_sig[base + (size_t)(g*8+j)*R_];
#pragma unroll
        for (int j = 0; j < 8; j++) {
            float o = fmaf(e, p, v[j]);
            g_sig[base + (size_t)(g*8+j)*R_] = __uint_as_float(f2tf32(o));
            p *= ret;
            last = o;   // exact fp32 for final_state
        }
    }
    if (write_fs && ch == NCH-1)
        fs_out[b*R_ + r] = last;
}

// ---- K5: output GEMM: acc(tf32) @ out_w^T(tf32) ----
__global__ __launch_bounds__(256) void k5_output(float* __restrict__ out) {
    extern __shared__ float smem[];
    float* As = smem;
    float* Bs = smem + 2*STAGE_F;
    uint32_t as_b = (uint32_t)__cvta_generic_to_shared(As);
    uint32_t bs_b = (uint32_t)__cvta_generic_to_shared(Bs);

    int nbase = blockIdx.x * 128;
    int mbase = blockIdx.y * 128;
    int t = threadIdx.x;
    int warp = t >> 5, lane = t & 31;
    int wm = warp >> 2, wn = warp & 3;
    int grp = lane >> 2, tid4 = lane & 3;
    int lrow = t >> 3, lk = (t & 7) * 4;

    float c[4][4][4];
#pragma unroll
    for (int mt = 0; mt < 4; mt++)
#pragma unroll
        for (int nt = 0; nt < 4; nt++)
#pragma unroll
            for (int i = 0; i < 4; i++) c[mt][nt][i] = 0.f;

    const float* Ag = g_sig + (size_t)mbase * R_;
    const float* Bg = g_outwt + (size_t)nbase * R_;

    auto prefetch = [&](int st, int k0) {
        uint32_t ao = as_b + (uint32_t)(st*STAGE_F)*4u;
        uint32_t bo = bs_b + (uint32_t)(st*STAGE_F)*4u;
#pragma unroll
        for (int i = 0; i < 4; i++) {
            int row = lrow + i*32;
            cp16(ao + (uint32_t)(row*LDT + lk)*4u, Ag + (size_t)row*R_ + k0 + lk);
            cp16(bo + (uint32_t)(row*LDT + lk)*4u, Bg + (size_t)row*R_ + k0 + lk);
        }
        asm volatile("cp.async.commit_group;\n");
    };

    prefetch(0, 0);
    const int NK = R_ / 32;   // 8
    for (int kt = 0; kt < NK; kt++) {
        if (kt + 1 < NK) {
            prefetch((kt+1)&1, (kt+1)*32);
            asm volatile("cp.async.wait_group 1;\n");
        } else {
            asm volatile("cp.async.wait_group 0;\n");
        }
        __syncthreads();
        gemm_compute_stage<false>(As + (kt&1)*STAGE_F, Bs + (kt&1)*STAGE_F,
                                  wm, wn, grp, tid4, c);
        __syncthreads();
    }

#pragma unroll
    for (int mt = 0; mt < 4; mt++) {
        int m0 = mbase + wm*64 + mt*16 + grp;
#pragma unroll
        for (int nt = 0; nt < 4; nt++) {
            int n = nbase + wn*32 + nt*8 + tid4*2;
            float2 v0 = make_float2(c[mt][nt][0], c[mt][nt][1]);
            float2 v1 = make_float2(c[mt][nt][2], c[mt][nt][3]);
            *(float2*)&out[(size_t)m0*D_ + n]     = v0;
            *(float2*)&out[(size_t)(m0+8)*D_ + n] = v1;
        }
    }
}

extern "C" void kernel_launch(void* const* d_in, const int* in_sizes, int n_in,
                              void* d_out, int out_size) {
    const float* x     = (const float*)d_in[0];
    const float* prev  = (const float*)d_in[1];
    const float* freq  = (const float*)d_in[2];
    const float* rbias = (const float*)d_in[3];
    const float* rw    = (const float*)d_in[4];
    const float* gw    = (const float*)d_in[5];
    const float* gbias = (const float*)d_in[6];
    const float* outw  = (const float*)d_in[7];
    float* out = (float*)d_out;

    const int SMEM_GEMM = 4 * STAGE_F * 4;   // 73728 bytes
    cudaFuncSetAttribute(k3_resonance, cudaFuncAttributeMaxDynamicSharedMemorySize, SMEM_GEMM);
    cudaFuncSetAttribute(k5_output,    cudaFuncAttributeMaxDynamicSharedMemorySize, SMEM_GEMM);

    const int out_elems = B_*S_*D_;
    int write_fs = (out_size >= out_elems + B_*R_) ? 1 : 0;
    float* fs = out + out_elems;

    k0_zero<<<8, 1024>>>();
    k1_stats<<<256, 256>>>(x);
    k2_prep<<<256, 256>>>(freq, rbias, rw, gw, gbias);
    k2b_roundw<<<(D_*R_)/256, 256>>>(outw);
    k3_resonance<<<dim3(2, 256), 256, SMEM_GEMM>>>(x);
    k_scan1<<<B_*NCH, 256>>>();
    k_scan2<<<B_*NCH, 256>>>(prev, fs, write_fs);
    k5_output<<<dim3(8, 256), 256, SMEM_GEMM>>>(out);
}